// round 14
// baseline (speedup 1.0000x reference)
#include <cuda_runtime.h>

// NetNew_17162689315115 — R14: R13 (all-constant LDC weights) with layers
// 2+3 offloaded to SHARED memory to de-saturate the constant port
// (82% -> ~66% util) while keeping L1/LDS path lightly loaded (~38%).
// FMA pipe becomes the sole binder. Exact rows + peel/tail everywhere;
// numerics identical to R1 (ascending-k accumulation).

struct NetParams {
    const float* x;
    const float* W2;     // layer-2 weights (13 x 26), staged to smem
    const float* W3;     // layer-3 weights (13 x 35), staged to smem
    float*       out;
    int          B;
};
struct PrepParams {
    const float* W[9];   // W1..W8, Wf
};

template <int L> struct LC {
    static constexpr int DIN  = 8 + 9 * L;
    static constexpr int BASE = 72 - 9 * L;   // first input feature index
};

// constant side: L0,L1,L4,L5,L6,L7 exact rows, then Wf
static constexpr int C_L0 = 0;
static constexpr int C_L1 = C_L0 + 13 * LC<0>::DIN;   // 104
static constexpr int C_L4 = C_L1 + 13 * LC<1>::DIN;   // 325
static constexpr int C_L5 = C_L4 + 13 * LC<4>::DIN;   // 897
static constexpr int C_L6 = C_L5 + 13 * LC<5>::DIN;   // 1586
static constexpr int C_L7 = C_L6 + 13 * LC<6>::DIN;   // 2392
static constexpr int WF_OFF   = C_L7 + 13 * LC<7>::DIN; // 3315
static constexpr int CW_TOTAL = WF_OFF + 80;            // 3395
template <int L> struct COff;
template <> struct COff<0> { static constexpr int V = C_L0; };
template <> struct COff<1> { static constexpr int V = C_L1; };
template <> struct COff<4> { static constexpr int V = C_L4; };
template <> struct COff<5> { static constexpr int V = C_L5; };
template <> struct COff<6> { static constexpr int V = C_L6; };
template <> struct COff<7> { static constexpr int V = C_L7; };

// shared side: L2 at 0 (338 floats), L3 at 340 (16B-aligned), total 800
static constexpr int S_L2 = 0;
static constexpr int S_L3 = (S_L2 + 13 * LC<2>::DIN + 3) & ~3;  // 340
static constexpr int SM_FLOATS = S_L3 + 13 * LC<3>::DIN + 1;    // 796
template <int L> struct SOff;
template <> struct SOff<2> { static constexpr int V = S_L2; };
template <> struct SOff<3> { static constexpr int V = S_L3; };

__constant__ __align__(16) float cw[CW_TOTAL];
__device__   __align__(16) float g_wpad[CW_TOTAL];

__device__ __forceinline__ float clip_mag(float v, float mx) {
    // matches jnp.where(|v| >= mx, v * |mx/v|, v) incl. inf -> NaN edge case
    if (fabsf(v) >= mx) v = v * fabsf(mx / v);
    return v;
}

// ---- prep: concatenate L0,L1,L4..L7 rows ++ Wf into scratch (const image) --
__global__ void netnew_prep(PrepParams pp) {
#define STAGE(L)                                                              \
    {                                                                         \
        constexpr int N = 13 * LC<L>::DIN;                                    \
        const float* g = pp.W[L];                                             \
        for (int i = threadIdx.x; i < N; i += blockDim.x)                     \
            g_wpad[COff<L>::V + i] = g[i];                                    \
    }
    STAGE(0) STAGE(1) STAGE(4) STAGE(5) STAGE(6) STAGE(7)
#undef STAGE
    for (int i = threadIdx.x; i < 80; i += blockDim.x)
        g_wpad[WF_OFF + i] = pp.W[8][i];
}

// ---- elementwise epilogue (identical order to R1) ----
__device__ __forceinline__ void apply_ops(const float* __restrict__ z,
                                          float* __restrict__ o) {
    o[0] = z[0] + z[1];
    o[1] = z[2] - z[3];
    o[2] = clip_mag(z[4] * z[5], 99999999.0f);
    {
        float b   = z[7];
        float den = (b == 0.0f) ? (b + 0.0001f) : b;
        o[3] = clip_mag(z[6] / den, 9999.0f);
    }
    o[4] = sinf(z[8]);
    o[5] = cosf(z[9]);
    {
        float a = z[10];
        if (a >= 17.0f) a = a * (17.0f / a);
        o[6] = expf(a);
    }
    o[7] = logf(fabsf(z[11]));
    o[8] = clip_mag(z[12] * z[12], 99999999.0f);
}

// ---- generic GEMV row body over an arbitrary base pointer ----
template <int DIN, int BASE, int ROFF, typename PtrT>
__device__ __forceinline__ float dot_row(const float* __restrict__ h, PtrT w) {
    float acc = 0.0f;
    int k = 0;
    const int mis = ROFF & 3;                 // compile-time
    if (mis != 0) {
        const int peel = 4 - mis;
#pragma unroll
        for (int t = 0; t < 3; ++t) {
            if (t < peel && k < DIN) {
                acc = fmaf(w[ROFF + k], h[BASE + k], acc);
                ++k;
            }
        }
    }
#pragma unroll
    for (; k + 3 < DIN; k += 4) {
        const float4 v = *reinterpret_cast<const float4*>(&w[ROFF + k]);
        acc = fmaf(v.x, h[BASE + k + 0], acc);
        acc = fmaf(v.y, h[BASE + k + 1], acc);
        acc = fmaf(v.z, h[BASE + k + 2], acc);
        acc = fmaf(v.w, h[BASE + k + 3], acc);
    }
#pragma unroll
    for (; k < DIN; ++k)
        acc = fmaf(w[ROFF + k], h[BASE + k], acc);
    return acc;
}

// helper to expand j = 0..12 with compile-time row offsets
template <int L, int OFFV, typename PtrT>
__device__ __forceinline__ void do_layer_any(float* __restrict__ h, PtrT w) {
    constexpr int DIN  = LC<L>::DIN;
    constexpr int BASE = LC<L>::BASE;
    float z[13];
#define ROW(J) z[J] = dot_row<DIN, BASE, OFFV + (J) * DIN>(h, w)
    ROW(0); ROW(1); ROW(2); ROW(3); ROW(4); ROW(5); ROW(6);
    ROW(7); ROW(8); ROW(9); ROW(10); ROW(11); ROW(12);
#undef ROW
    apply_ops(z, h + (BASE - 9));
}

__global__ __launch_bounds__(128, 7)
void netnew_kernel14(NetParams p) {
    __shared__ __align__(16) float smw[SM_FLOATS];

    // stage L2/L3 weights (exact row-major) into shared
    for (int i = threadIdx.x; i < 13 * LC<2>::DIN; i += 128)
        smw[S_L2 + i] = p.W2[i];
    for (int i = threadIdx.x; i < 13 * LC<3>::DIN; i += 128)
        smw[S_L3 + i] = p.W3[i];
    __syncthreads();

    const int row = blockIdx.x * blockDim.x + threadIdx.x;
    if (row >= p.B) return;

    // h layout: [outs8 | outs7 | ... | outs1 | x]; x at [72..79].
    float h[80];
    {
        const float4* xr = reinterpret_cast<const float4*>(p.x + (size_t)row * 8);
        float4 a = xr[0], b = xr[1];
        h[72] = a.x; h[73] = a.y; h[74] = a.z; h[75] = a.w;
        h[76] = b.x; h[77] = b.y; h[78] = b.z; h[79] = b.w;
    }

    do_layer_any<0, C_L0>(h, (const float*)cw);
    do_layer_any<1, C_L1>(h, (const float*)cw);
    do_layer_any<2, S_L2>(h, (const float*)smw);
    do_layer_any<3, S_L3>(h, (const float*)smw);
    do_layer_any<4, C_L4>(h, (const float*)cw);
    do_layer_any<5, C_L5>(h, (const float*)cw);
    do_layer_any<6, C_L6>(h, (const float*)cw);
    do_layer_any<7, C_L7>(h, (const float*)cw);

    // final: out = dot(Wf, h[0..79]), sequential ascending k (WF_OFF%4!=0?
    // WF_OFF=3315 -> mis=3; handled by the same peel machinery)
    float acc = dot_row<80, 0, WF_OFF>(h, (const float*)cw);
    p.out[row] = acc;
}

extern "C" void kernel_launch(void* const* d_in, const int* in_sizes, int n_in,
                              void* d_out, int out_size) {
    PrepParams pp;
    for (int i = 0; i < 9; ++i) pp.W[i] = (const float*)d_in[1 + i];

    NetParams p;
    p.x   = (const float*)d_in[0];
    p.W2  = (const float*)d_in[3];   // W3 input = layer index 2
    p.W3  = (const float*)d_in[4];   // W4 input = layer index 3
    p.out = (float*)d_out;
    p.B   = in_sizes[0] / 8;

    // stage constant image, then ONE D2D copy into the constant bank
    netnew_prep<<<1, 256>>>(pp);
    void* src = nullptr;
    cudaGetSymbolAddress(&src, g_wpad);
    cudaMemcpyToSymbolAsync(cw, src, CW_TOTAL * sizeof(float), 0,
                            cudaMemcpyDeviceToDevice, 0);

    const int threads = 128;
    const int blocks  = (p.B + threads - 1) / threads;
    netnew_kernel14<<<blocks, threads>>>(p);
}

// round 15
// speedup vs baseline: 1.0455x; 1.0455x over previous
#include <cuda_runtime.h>

// NetNew_17162689315115 — R15: R13 + (a) rows padded to x4 so ALL weight
// loads are LDC.128 (kills ~235 scalar LDCs that each cost a full rt=8
// constant-port slot), (b) launch_bounds(192,5) -> 30 warps/SM (68-reg cap,
// small spills onto the idle L1 path). Numerics identical to R1/R6.

struct NetParams {
    const float* x;
    float*       out;
    int          B;
};
struct PrepParams {
    const float* W[9];   // W1..W8, Wf
};

template <int L> struct LC {
    static constexpr int DIN  = 8 + 9 * L;
    static constexpr int DPAD = (DIN + 3) & ~3;
    static constexpr int BASE = 72 - 9 * L;   // first input feature index
};
template <int L> struct WOff;
template <> struct WOff<0> { static constexpr int V = 0; };
template <int L> struct WOff {
    static constexpr int V = WOff<L - 1>::V + 13 * LC<L - 1>::DPAD;
};
static constexpr int WF_OFF   = WOff<7>::V + 13 * LC<7>::DPAD;  // 4264
static constexpr int CW_TOTAL = WF_OFF + 80;                    // 4344

__constant__ __align__(16) float cw[CW_TOTAL];
__device__   __align__(16) float g_wpad[CW_TOTAL];

__device__ __forceinline__ float clip_mag(float v, float mx) {
    // matches jnp.where(|v| >= mx, v * |mx/v|, v) incl. inf -> NaN edge case
    if (fabsf(v) >= mx) v = v * fabsf(mx / v);
    return v;
}

// ---- prep: pad each W row to DPAD (zero fill), append Wf ----
__global__ void netnew_prep(PrepParams pp) {
#define STAGE(L)                                                              \
    {                                                                         \
        constexpr int D  = LC<L>::DIN;                                        \
        constexpr int DP = LC<L>::DPAD;                                       \
        const float* g = pp.W[L];                                             \
        for (int i = threadIdx.x; i < 13 * DP; i += blockDim.x) {             \
            int r = i / DP, c = i - r * DP;                                   \
            g_wpad[WOff<L>::V + i] = (c < D) ? g[r * D + c] : 0.0f;           \
        }                                                                     \
    }
    STAGE(0) STAGE(1) STAGE(2) STAGE(3) STAGE(4) STAGE(5) STAGE(6) STAGE(7)
#undef STAGE
    for (int i = threadIdx.x; i < 80; i += blockDim.x)
        g_wpad[WF_OFF + i] = pp.W[8][i];
}

template <int L>
__device__ __forceinline__ void do_layer(float* __restrict__ h) {
    constexpr int DP   = LC<L>::DPAD;
    constexpr int BASE = LC<L>::BASE;

    float z[13];
#pragma unroll
    for (int j = 0; j < 13; ++j) {
        float acc = 0.0f;
#pragma unroll
        for (int k = 0; k < DP; k += 4) {
            const float4 w =
                *reinterpret_cast<const float4*>(cw + WOff<L>::V + j * DP + k);
            acc = fmaf(w.x, h[BASE + k + 0], acc);
            acc = fmaf(w.y, h[BASE + k + 1], acc);
            acc = fmaf(w.z, h[BASE + k + 2], acc);
            acc = fmaf(w.w, h[BASE + k + 3], acc);
        }
        z[j] = acc;
    }

    float* o = h + (BASE - 9);
    o[0] = z[0] + z[1];
    o[1] = z[2] - z[3];
    o[2] = clip_mag(z[4] * z[5], 99999999.0f);
    {
        float b   = z[7];
        float den = (b == 0.0f) ? (b + 0.0001f) : b;
        o[3] = clip_mag(z[6] / den, 9999.0f);
    }
    o[4] = sinf(z[8]);
    o[5] = cosf(z[9]);
    {
        float a = z[10];
        if (a >= 17.0f) a = a * (17.0f / a);
        o[6] = expf(a);
    }
    o[7] = logf(fabsf(z[11]));
    o[8] = clip_mag(z[12] * z[12], 99999999.0f);
}

__global__ __launch_bounds__(192, 5)
void netnew_kernel15(NetParams p) {
    const int row = blockIdx.x * blockDim.x + threadIdx.x;
    if (row >= p.B) return;

    // h layout: [outs8 | outs7 | ... | outs1 | x]; x at [72..79];
    // [80..83] zero pads read by padded (zero) weight lanes.
    float h[84];
    {
        const float4* xr = reinterpret_cast<const float4*>(p.x + (size_t)row * 8);
        float4 a = xr[0], b = xr[1];
        h[72] = a.x; h[73] = a.y; h[74] = a.z; h[75] = a.w;
        h[76] = b.x; h[77] = b.y; h[78] = b.z; h[79] = b.w;
        h[80] = 0.0f; h[81] = 0.0f; h[82] = 0.0f; h[83] = 0.0f;
    }

    do_layer<0>(h);
    do_layer<1>(h);
    do_layer<2>(h);
    do_layer<3>(h);
    do_layer<4>(h);
    do_layer<5>(h);
    do_layer<6>(h);
    do_layer<7>(h);

    // final: out = dot(Wf, h[0..79]), sequential ascending k (WF_OFF%4==0)
    float acc = 0.0f;
#pragma unroll
    for (int k = 0; k < 80; k += 4) {
        const float4 w = *reinterpret_cast<const float4*>(cw + WF_OFF + k);
        acc = fmaf(w.x, h[k + 0], acc);
        acc = fmaf(w.y, h[k + 1], acc);
        acc = fmaf(w.z, h[k + 2], acc);
        acc = fmaf(w.w, h[k + 3], acc);
    }
    p.out[row] = acc;
}

extern "C" void kernel_launch(void* const* d_in, const int* in_sizes, int n_in,
                              void* d_out, int out_size) {
    PrepParams pp;
    for (int i = 0; i < 9; ++i) pp.W[i] = (const float*)d_in[1 + i];

    NetParams p;
    p.x   = (const float*)d_in[0];
    p.out = (float*)d_out;
    p.B   = in_sizes[0] / 8;

    // stage padded weights, then ONE D2D copy into the constant bank
    netnew_prep<<<1, 256>>>(pp);
    void* src = nullptr;
    cudaGetSymbolAddress(&src, g_wpad);
    cudaMemcpyToSymbolAsync(cw, src, CW_TOTAL * sizeof(float), 0,
                            cudaMemcpyDeviceToDevice, 0);

    const int threads = 192;
    const int blocks  = (p.B + threads - 1) / threads;
    netnew_kernel15<<<blocks, threads>>>(p);
}

// round 16
// speedup vs baseline: 1.0787x; 1.0318x over previous
#include <cuda_runtime.h>

// NetNew_17162689315115 — R16: flat-stream constant weights.
// Per layer, the 13xDIN weight block is contiguous and 16B-aligned at the
// LAYER level; it is streamed as LDC.128s whose 4 lanes are routed to the
// right (j,k) accumulator at compile time (loads legally span row
// boundaries). No pad FMAs, no scalar LDCs: FFMA=4188, LDC.128~=1047.
// h[80] register-resident, launch_bounds(128,7). Numerics == R1.

struct NetParams {
    const float* x;
    float*       out;
    int          B;
};
struct PrepParams {
    const float* W[9];   // W1..W8, Wf
};

template <int L> struct LC {
    static constexpr int DIN  = 8 + 9 * L;
    static constexpr int NTOT = 13 * DIN;
    static constexpr int N4   = (NTOT + 3) & ~3;   // padded block length
    static constexpr int BASE = 72 - 9 * L;        // first input feature index
};
template <int L> struct LOff;
template <> struct LOff<0> { static constexpr int V = 0; };
template <int L> struct LOff {
    static constexpr int V = LOff<L - 1>::V + LC<L - 1>::N4;
};
static constexpr int WF_OFF   = LOff<7>::V + LC<7>::N4;   // 4120
static constexpr int CW_TOTAL = WF_OFF + 80;              // 4200

__constant__ __align__(16) float cw[CW_TOTAL];
__device__   __align__(16) float g_wpad[CW_TOTAL];

__device__ __forceinline__ float clip_mag(float v, float mx) {
    // matches jnp.where(|v| >= mx, v * |mx/v|, v) incl. inf -> NaN edge case
    if (fabsf(v) >= mx) v = v * fabsf(mx / v);
    return v;
}

// ---- prep: copy each layer block (exact, contiguous) + zero block pads ----
__global__ void netnew_prep(PrepParams pp) {
#define STAGE(L)                                                              \
    {                                                                         \
        constexpr int N  = LC<L>::NTOT;                                       \
        constexpr int N4 = LC<L>::N4;                                         \
        const float* g = pp.W[L];                                             \
        for (int i = threadIdx.x; i < N4; i += blockDim.x)                    \
            g_wpad[LOff<L>::V + i] = (i < N) ? g[i] : 0.0f;                   \
    }
    STAGE(0) STAGE(1) STAGE(2) STAGE(3) STAGE(4) STAGE(5) STAGE(6) STAGE(7)
#undef STAGE
    for (int i = threadIdx.x; i < 80; i += blockDim.x)
        g_wpad[WF_OFF + i] = pp.W[8][i];
}

template <int L>
__device__ __forceinline__ void do_layer(float* __restrict__ h) {
    constexpr int DIN  = LC<L>::DIN;
    constexpr int NTOT = LC<L>::NTOT;
    constexpr int N4   = LC<L>::N4;
    constexpr int BASE = LC<L>::BASE;

    float z[13];
#pragma unroll
    for (int j = 0; j < 13; ++j) z[j] = 0.0f;

#pragma unroll
    for (int i4 = 0; i4 < N4; i4 += 4) {
        const float4 w = *reinterpret_cast<const float4*>(cw + LOff<L>::V + i4);
#pragma unroll
        for (int e = 0; e < 4; ++e) {
            const int i = i4 + e;                 // compile-time
            if (i < NTOT) {
                const int j = i / DIN;            // compile-time
                const int k = i - j * DIN;        // compile-time
                const float wv = (e == 0) ? w.x : (e == 1) ? w.y
                               : (e == 2) ? w.z : w.w;
                z[j] = fmaf(wv, h[BASE + k], z[j]);
            }
        }
    }

    float* o = h + (BASE - 9);
    o[0] = z[0] + z[1];
    o[1] = z[2] - z[3];
    o[2] = clip_mag(z[4] * z[5], 99999999.0f);
    {
        float b   = z[7];
        float den = (b == 0.0f) ? (b + 0.0001f) : b;
        o[3] = clip_mag(z[6] / den, 9999.0f);
    }
    o[4] = sinf(z[8]);
    o[5] = cosf(z[9]);
    {
        float a = z[10];
        if (a >= 17.0f) a = a * (17.0f / a);
        o[6] = expf(a);
    }
    o[7] = logf(fabsf(z[11]));
    o[8] = clip_mag(z[12] * z[12], 99999999.0f);
}

__global__ __launch_bounds__(128, 7)
void netnew_kernel16(NetParams p) {
    const int row = blockIdx.x * blockDim.x + threadIdx.x;
    if (row >= p.B) return;

    // h layout: [outs8 | outs7 | ... | outs1 | x]; x at [72..79].
    float h[80];
    {
        const float4* xr = reinterpret_cast<const float4*>(p.x + (size_t)row * 8);
        float4 a = xr[0], b = xr[1];
        h[72] = a.x; h[73] = a.y; h[74] = a.z; h[75] = a.w;
        h[76] = b.x; h[77] = b.y; h[78] = b.z; h[79] = b.w;
    }

    do_layer<0>(h);
    do_layer<1>(h);
    do_layer<2>(h);
    do_layer<3>(h);
    do_layer<4>(h);
    do_layer<5>(h);
    do_layer<6>(h);
    do_layer<7>(h);

    // final: out = dot(Wf, h[0..79]), sequential ascending k (WF_OFF%4==0)
    float acc = 0.0f;
#pragma unroll
    for (int k = 0; k < 80; k += 4) {
        const float4 w = *reinterpret_cast<const float4*>(cw + WF_OFF + k);
        acc = fmaf(w.x, h[k + 0], acc);
        acc = fmaf(w.y, h[k + 1], acc);
        acc = fmaf(w.z, h[k + 2], acc);
        acc = fmaf(w.w, h[k + 3], acc);
    }
    p.out[row] = acc;
}

extern "C" void kernel_launch(void* const* d_in, const int* in_sizes, int n_in,
                              void* d_out, int out_size) {
    PrepParams pp;
    for (int i = 0; i < 9; ++i) pp.W[i] = (const float*)d_in[1 + i];

    NetParams p;
    p.x   = (const float*)d_in[0];
    p.out = (float*)d_out;
    p.B   = in_sizes[0] / 8;

    // stage flat weight image, then ONE D2D copy into the constant bank
    netnew_prep<<<1, 256>>>(pp);
    void* src = nullptr;
    cudaGetSymbolAddress(&src, g_wpad);
    cudaMemcpyToSymbolAsync(cw, src, CW_TOTAL * sizeof(float), 0,
                            cudaMemcpyDeviceToDevice, 0);

    const int threads = 128;
    const int blocks  = (p.B + threads - 1) / threads;
    netnew_kernel16<<<blocks, threads>>>(p);
}